// round 6
// baseline (speedup 1.0000x reference)
#include <cuda_runtime.h>
#include <cuda_fp16.h>
#include <mma.h>
#include <cstdint>

using namespace nvcuda;

// Problem constants
#define B_DIM    32
#define S_DIM    2048
#define H_DIM    4096
#define R_DIM    64
#define TILE_M   128
#define KC       32                    // K elements per chunk
#define NCHUNK   (H_DIM / KC)          // 128
#define NSTAGE   6
#define NTHREADS 384                   // 8 consumer warps + 4 producer warps

// SMEM (half): row stride 40 halves = 80 B (conflict-free, ldm multiple of 8)
#define LDH        40
#define X_STAGE_H  (TILE_M * LDH)                  // 5120 halves = 10240 B
#define W_STAGE_H  (R_DIM * LDH)                   // 2560 halves = 5120 B
#define STAGE_H    (X_STAGE_H + W_STAGE_H)         // 7680 halves
#define STAGE_B    (STAGE_H * 2)                   // 15360 B
#define SMEM_BUF   128                             // 12 mbarriers
#define SMEM_TOTAL (SMEM_BUF + NSTAGE * STAGE_B)   // 92288 B (x2 CTAs = 184576)

__device__ __forceinline__ uint32_t smem_u32(const void* p) {
    uint32_t r;
    asm("{ .reg .u64 t; cvta.to.shared.u64 t, %1; cvt.u32.u64 %0, t; }"
        : "=r"(r) : "l"(p));
    return r;
}

__device__ __forceinline__ void sts64(uint32_t addr, uint32_t a, uint32_t b) {
    asm volatile("st.shared.v2.b32 [%0], {%1, %2};"
                 :: "r"(addr), "r"(a), "r"(b));
}

#define MBAR_INIT(addr, cnt) \
    asm volatile("mbarrier.init.shared.b64 [%0], %1;" \
                 :: "r"(addr), "r"(cnt) : "memory")

#define MBAR_ARRIVE(addr) \
    asm volatile("mbarrier.arrive.shared.b64 _, [%0];" \
                 :: "r"(addr) : "memory")

__device__ __forceinline__ void mbar_wait(uint32_t addr, uint32_t parity) {
    uint32_t done;
    asm volatile(
        "{\n\t.reg .pred p;\n\t"
        "mbarrier.try_wait.parity.acquire.cta.shared::cta.b64 p, [%1], %2;\n\t"
        "selp.b32 %0, 1, 0, p;\n\t}"
        : "=r"(done) : "r"(addr), "r"(parity) : "memory");
    if (!done) {
        asm volatile(
            "{\n\t.reg .pred P1;\n\t"
            "WAIT_LOOP_%=:\n\t"
            "mbarrier.try_wait.parity.acquire.cta.shared::cta.b64 P1, [%0], %1, 0x989680;\n\t"
            "@P1 bra.uni WAIT_DONE_%=;\n\t"
            "bra.uni WAIT_LOOP_%=;\n\t"
            "WAIT_DONE_%=:\n\t}"
            :: "r"(addr), "r"(parity) : "memory");
    }
}

__global__ void __launch_bounds__(NTHREADS, 2)
multilora_fp16_ws_kernel(const float* __restrict__ x,
                         const int* __restrict__ adapter_ids,
                         const float* __restrict__ weight,
                         float* __restrict__ out) {
    extern __shared__ __align__(16) __half smem[];
    const uint32_t smem_base = smem_u32(smem);
    __half* buf = smem + SMEM_BUF / 2;

    const int tid = threadIdx.x;
    const int wid = tid >> 5;

    const int mtile = blockIdx.x;       // 0..15
    const int b     = blockIdx.y;       // 0..31
    const int m0    = mtile * TILE_M;

    // mbarriers: full[s] at 8*s, empty[s] at 48 + 8*s
    const uint32_t FULL0  = smem_base;
    const uint32_t EMPTY0 = smem_base + 48;

    if (tid == 0) {
        #pragma unroll
        for (int s = 0; s < NSTAGE; s++) {
            MBAR_INIT(FULL0  + 8 * s, 128);   // 128 producer threads arrive
            MBAR_INIT(EMPTY0 + 8 * s, 256);   // 256 consumer threads arrive
        }
    }
    __syncthreads();

    if (wid < 8) {
        // ================ CONSUMER: 8 warps, 32x32 WMMA fp16 tiles ==========
        // Pre-arm empty barriers: completes phase 0 so producers' first
        // empty-waits (parity 0) pass immediately for all NSTAGE slots.
        #pragma unroll
        for (int s = 0; s < NSTAGE; s++)
            MBAR_ARRIVE(EMPTY0 + 8 * s);

        const int wm = wid >> 1;
        const int wn = wid & 1;

        wmma::fragment<wmma::accumulator, 16, 16, 16, float> acc[2][2];
        #pragma unroll
        for (int fi = 0; fi < 2; fi++)
            #pragma unroll
            for (int fj = 0; fj < 2; fj++)
                wmma::fill_fragment(acc[fi][fj], 0.0f);

        int s = 0;
        uint32_t parity = 0;
        for (int kc = 0; kc < NCHUNK; kc++) {
            mbar_wait(FULL0 + 8 * s, parity);

            const __half* xs = buf + s * STAGE_H;
            const __half* ws = xs + X_STAGE_H;

            #pragma unroll
            for (int kk = 0; kk < KC; kk += 16) {
                wmma::fragment<wmma::matrix_a, 16, 16, 16, __half,
                               wmma::row_major> af[2];
                wmma::fragment<wmma::matrix_b, 16, 16, 16, __half,
                               wmma::col_major> bf[2];
                #pragma unroll
                for (int fi = 0; fi < 2; fi++)
                    wmma::load_matrix_sync(af[fi],
                        xs + (wm * 32 + fi * 16) * LDH + kk, LDH);
                #pragma unroll
                for (int fj = 0; fj < 2; fj++)
                    wmma::load_matrix_sync(bf[fj],
                        ws + (wn * 32 + fj * 16) * LDH + kk, LDH);
                #pragma unroll
                for (int fi = 0; fi < 2; fi++)
                    #pragma unroll
                    for (int fj = 0; fj < 2; fj++)
                        wmma::mma_sync(acc[fi][fj], af[fi], bf[fj], acc[fi][fj]);
            }

            MBAR_ARRIVE(EMPTY0 + 8 * s);
            if (++s == NSTAGE) { s = 0; parity ^= 1u; }
        }

        // epilogue: direct store, out is [B, S, R] row-major
        float* obase = out + ((size_t)(b * S_DIM + m0 + wm * 32)) * R_DIM + wn * 32;
        #pragma unroll
        for (int fi = 0; fi < 2; fi++)
            #pragma unroll
            for (int fj = 0; fj < 2; fj++)
                wmma::store_matrix_sync(obase + (size_t)fi * 16 * R_DIM + fj * 16,
                                        acc[fi][fj], R_DIM, wmma::mem_row_major);
    } else {
        // ================ PRODUCER: 4 warps, LDG -> CVT.RN -> STS ===========
        const int ptid = tid - 256;                  // 0..127
        const int aid  = __ldg(adapter_ids + b);
        const int prow = ptid >> 3;                  // 0..15
        const int q    = ptid & 7;

        // x quads j=0..7: row = prow + 16j; w quads j=0..3: row = prow + 16j
        const float* xbase = x + ((size_t)(b * S_DIM + m0 + prow)) * H_DIM + q * 4;
        const float* wbase = weight + ((size_t)(aid * R_DIM + prow)) * H_DIM + q * 4;

        uint32_t xoff[8], woff[4];
        #pragma unroll
        for (int j = 0; j < 8; j++)
            xoff[j] = (uint32_t)(SMEM_BUF + ((prow + 16 * j) * LDH + q * 4) * 2);
        #pragma unroll
        for (int j = 0; j < 4; j++)
            woff[j] = (uint32_t)(SMEM_BUF +
                      (X_STAGE_H + (prow + 16 * j) * LDH + q * 4) * 2);

        int s = 0;
        uint32_t parity = 0;
        for (int kc = 0; kc < NCHUNK; kc++) {
            const uint32_t sbase = smem_base + s * STAGE_B;
            const size_t gk = (size_t)kc * KC;

            mbar_wait(EMPTY0 + 8 * s, parity);

            // batched loads (high MLP), then convert + store
            float4 vx[8];
            #pragma unroll
            for (int j = 0; j < 8; j++)
                vx[j] = *(const float4*)(xbase + (size_t)j * 16 * H_DIM + gk);
            float4 vw[4];
            #pragma unroll
            for (int j = 0; j < 4; j++)
                vw[j] = *(const float4*)(wbase + (size_t)j * 16 * H_DIM + gk);

            #pragma unroll
            for (int j = 0; j < 8; j++) {
                __half2 h0 = __floats2half2_rn(vx[j].x, vx[j].y);
                __half2 h1 = __floats2half2_rn(vx[j].z, vx[j].w);
                sts64(sbase + xoff[j],
                      *(const uint32_t*)&h0, *(const uint32_t*)&h1);
            }
            #pragma unroll
            for (int j = 0; j < 4; j++) {
                __half2 h0 = __floats2half2_rn(vw[j].x, vw[j].y);
                __half2 h1 = __floats2half2_rn(vw[j].z, vw[j].w);
                sts64(sbase + woff[j],
                      *(const uint32_t*)&h0, *(const uint32_t*)&h1);
            }

            MBAR_ARRIVE(FULL0 + 8 * s);
            if (++s == NSTAGE) { s = 0; parity ^= 1u; }
        }
    }
}

extern "C" void kernel_launch(void* const* d_in, const int* in_sizes, int n_in,
                              void* d_out, int out_size) {
    const float* x   = (const float*)d_in[0];
    const int*   ids = (const int*)d_in[1];
    const float* w   = (const float*)d_in[2];
    float* out = (float*)d_out;

    const int b = in_sizes[1];   // number of requests (32)

    cudaFuncSetAttribute(multilora_fp16_ws_kernel,
                         cudaFuncAttributeMaxDynamicSharedMemorySize, SMEM_TOTAL);

    dim3 grid(S_DIM / TILE_M, b);
    multilora_fp16_ws_kernel<<<grid, NTHREADS, SMEM_TOTAL>>>(x, ids, w, out);
}